// round 12
// baseline (speedup 1.0000x reference)
#include <cuda_runtime.h>

// Spacial IRNN: 4 directional relu-scans over [B,C,H,W] = [4,64,256,256] fp32.
// out[dir][b][c][h][w], dir: 0=up, 1=right, 2=down, 3=left.
// h_0 = x_edge (raw), h_t = relu(w_c * h_{t-1} + b_c + x_t).
//
// R9 chassis (best: 75.8us) + L2 software prefetch to cut exposed DRAM
// latency (bytes-in-flight was the binding constraint at ~4.2 TB/s).
//   role = bid & 1:
//     0 -> vertical block, one direction per block (vb&1: 0=down, 1=up),
//          one thread per column; prefetch input PD rows ahead into L2.
//     1 -> horizontal block: warp-specialized, threads 0-127 "right" on
//          tile A, 128-255 "left" on tile B, own named barriers; float4 I/O
//          on stride-36 tiles; next chunk prefetched into L2 during load.

#define HH 256
#define WW 256
#define BB 4
#define CC 64

constexpr int HW = HH * WW;
constexpr long long DIRSZ = (long long)BB * CC * HH * WW;  // 16,777,216

constexpr int TPB    = 256;
constexpr int HROWS  = 128;
constexpr int CHUNK  = 32;
constexpr int NCHUNK = WW / CHUNK;              // 8
constexpr int STRIDE = 36;                      // floats; 144B row, 16B-aligned
constexpr int PD     = 12;                      // vertical prefetch distance

__device__ __forceinline__ void bar_group(int id) {
    asm volatile("bar.sync %0, 128;" :: "r"(id) : "memory");
}
__device__ __forceinline__ void prefetch_l2(const void* p) {
    asm volatile("prefetch.global.L2 [%0];" :: "l"(p));
}

__global__ void __launch_bounds__(TPB, 6)
irnn_fused_kernel(const float* __restrict__ x,
                  const float* __restrict__ w_up,    const float* __restrict__ b_up,
                  const float* __restrict__ w_right, const float* __restrict__ b_right,
                  const float* __restrict__ w_down,  const float* __restrict__ b_down,
                  const float* __restrict__ w_left,  const float* __restrict__ b_left,
                  float* __restrict__ out)
{
    __shared__ float tiles[2][HROWS * STRIDE];   // [0]=right(A), [1]=left(B)

    const int bid = blockIdx.x;
    const int tid = threadIdx.x;

    if ((bid & 1) == 0) {
        // ---------------- vertical: one direction, one thread per column ----
        const int vb   = bid >> 1;          // 0 .. 511
        const int isUp = vb & 1;            // 0 = down, 1 = up
        const int unit = vb >> 1;           // 0 .. 255

        const int id = unit * TPB + tid;    // 0 .. B*C*W-1
        const int w  = id & (WW - 1);
        const int bc = id >> 8;
        const int c  = bc & (CC - 1);

        const float* xp = x + (size_t)bc * HW + w;

        if (!isUp) {
            float* od = out + 2 * DIRSZ + (size_t)bc * HW + w;   // down
            const float wd = w_down[c], bd = b_down[c];
            float s = xp[0];
            __stcs(&od[0], s);
#pragma unroll 8
            for (int h = 1; h < HH; ++h) {
                int hp = h + PD < HH ? h + PD : HH - 1;
                prefetch_l2(&xp[hp * WW]);
                float xv = xp[h * WW];
                s = fmaxf(fmaf(wd, s, bd + xv), 0.0f);
                __stcs(&od[h * WW], s);
            }
        } else {
            float* ou = out + 0 * DIRSZ + (size_t)bc * HW + w;   // up
            const float wu = w_up[c], bu = b_up[c];
            float s = xp[(HH - 1) * WW];
            __stcs(&ou[(HH - 1) * WW], s);
#pragma unroll 8
            for (int h = HH - 2; h >= 0; --h) {
                int hp = h - PD >= 0 ? h - PD : 0;
                prefetch_l2(&xp[hp * WW]);
                float xv = xp[h * WW];
                s = fmaxf(fmaf(wu, s, bu + xv), 0.0f);
                __stcs(&ou[h * WW], s);
            }
        }
    } else {
        // ------------------- horizontal: 128 rows, warp-specialized ---------
        const int hb = bid >> 1;                 // 0 .. 511
        const int r0 = hb * HROWS;               // first global row
        const int bc = r0 >> 8;                  // uniform within block
        const int c  = bc & (CC - 1);

        const bool isLeft = (tid >= HROWS);
        const int  gt     = tid & (HROWS - 1);   // thread id within group
        const int  barid  = isLeft ? 2 : 1;

        const float* xbase = x + (size_t)r0 * WW;
        float* obase = out + (isLeft ? 3 : 1) * DIRSZ + (size_t)r0 * WW;

        const float wsc = isLeft ? w_left[c] : w_right[c];
        const float bsc = isLeft ? b_left[c] : b_right[c];

        float* tile = &tiles[isLeft ? 1 : 0][0];

        // staging map: f = k*128 + gt ; row = f>>3 ; col4 = f&7
        const int srow  = gt >> 3;               // base row, +16 per k
        const int scol4 = gt & 7;

        float s = 0.0f;
        for (int ch = 0; ch < NCHUNK; ++ch) {
            // right walks chunks forward, left backward
            const int wX = (isLeft ? (NCHUNK - 1 - ch) : ch) * CHUNK;
            // next chunk this group will touch (clamped at the last chunk)
            const int chn = (ch < NCHUNK - 1) ? ch + 1 : ch;
            const int wN  = (isLeft ? (NCHUNK - 1 - chn) : chn) * CHUNK;

            // ---- load: LDG.128 -> STS.128; prefetch next chunk to L2 ----
#pragma unroll
            for (int k = 0; k < 8; ++k) {
                int row = srow + k * 16;
                prefetch_l2(&xbase[(size_t)row * WW + wN + scol4 * 4]);
                float4 v = *(const float4*)&xbase[(size_t)row * WW + wX + scol4 * 4];
                *(float4*)&tile[row * STRIDE + scol4 * 4] = v;
            }
            bar_group(barid);

            // ---- scan owned row gt, register-resident in 8-float windows ---
            float* tr = &tile[gt * STRIDE];
            if (!isLeft) {
#pragma unroll
                for (int sb = 0; sb < 4; ++sb) {        // 4 sub-blocks of 8
                    float4 v0 = *(float4*)&tr[sb * 8];
                    float4 v1 = *(float4*)&tr[sb * 8 + 4];
                    float a[8] = {v0.x, v0.y, v0.z, v0.w, v1.x, v1.y, v1.z, v1.w};
#pragma unroll
                    for (int t = 0; t < 8; ++t) {
                        float xv = a[t];
                        if (ch == 0 && sb == 0 && t == 0) s = xv;
                        else s = fmaxf(fmaf(wsc, s, bsc + xv), 0.0f);
                        a[t] = s;
                    }
                    *(float4*)&tr[sb * 8]     = make_float4(a[0], a[1], a[2], a[3]);
                    *(float4*)&tr[sb * 8 + 4] = make_float4(a[4], a[5], a[6], a[7]);
                }
            } else {
#pragma unroll
                for (int sb = 3; sb >= 0; --sb) {
                    float4 v0 = *(float4*)&tr[sb * 8];
                    float4 v1 = *(float4*)&tr[sb * 8 + 4];
                    float a[8] = {v0.x, v0.y, v0.z, v0.w, v1.x, v1.y, v1.z, v1.w};
#pragma unroll
                    for (int t = 7; t >= 0; --t) {
                        float xv = a[t];
                        if (ch == 0 && sb == 3 && t == 7) s = xv;
                        else s = fmaxf(fmaf(wsc, s, bsc + xv), 0.0f);
                        a[t] = s;
                    }
                    *(float4*)&tr[sb * 8]     = make_float4(a[0], a[1], a[2], a[3]);
                    *(float4*)&tr[sb * 8 + 4] = make_float4(a[4], a[5], a[6], a[7]);
                }
            }
            bar_group(barid);

            // ---- store: LDS.128 -> STG.128 streaming ----
#pragma unroll
            for (int k = 0; k < 8; ++k) {
                int row = srow + k * 16;
                float4 v = *(float4*)&tile[row * STRIDE + scol4 * 4];
                __stcs((float4*)&obase[(size_t)row * WW + wX + scol4 * 4], v);
            }
            bar_group(barid);   // tile reads done before next chunk overwrites
        }
    }
}

extern "C" void kernel_launch(void* const* d_in, const int* in_sizes, int n_in,
                              void* d_out, int out_size)
{
    const float* x       = (const float*)d_in[0];
    const float* w_up    = (const float*)d_in[1];
    const float* w_right = (const float*)d_in[2];
    const float* w_down  = (const float*)d_in[3];
    const float* w_left  = (const float*)d_in[4];
    const float* b_up    = (const float*)d_in[5];
    const float* b_right = (const float*)d_in[6];
    const float* b_down  = (const float*)d_in[7];
    const float* b_left  = (const float*)d_in[8];
    float* out = (float*)d_out;

    // 512 vertical (256 down + 256 up) + 512 horizontal, interleaved by parity
    irnn_fused_kernel<<<1024, TPB>>>(x,
                                     w_up, b_up, w_right, b_right,
                                     w_down, b_down, w_left, b_left,
                                     out);
}

// round 14
// speedup vs baseline: 1.4606x; 1.4606x over previous
#include <cuda_runtime.h>

// Spacial IRNN: 4 directional relu-scans over [B,C,H,W] = [4,64,256,256] fp32.
// out[dir][b][c][h][w], dir: 0=up, 1=right, 2=down, 3=left.
// h_0 = x_edge (raw), h_t = relu(w_c * h_{t-1} + b_c + x_t).
//
// Single-wave max-TLP: 2048 blocks x 128 threads, 16 blocks/SM target
// (regs<=32, smem 8.2KB), one 256-step chain per thread everywhere.
//   bid even -> vertical: one direction per block (vb&1: 0=down, 1=up),
//               one thread per column, coalesced scalar I/O, stcs stores.
//   bid odd  -> horizontal: 64 rows; threads 0-63 scan "right" on tile A
//               (bar 1), threads 64-127 scan "left" on tile B (bar 2).
//               Dense 64x16 tiles (CHUNK=16), window swizzle
//               p = q ^ ((row>>1)&3): conflict-free staging AND scan.

#define HH 256
#define WW 256
#define BB 4
#define CC 64

constexpr int HW = HH * WW;
constexpr long long DIRSZ = (long long)BB * CC * HH * WW;  // 16,777,216

constexpr int TPB    = 128;
constexpr int HR     = 64;                      // rows per horizontal block
constexpr int CHUNK  = 16;
constexpr int NCHUNK = WW / CHUNK;              // 16

__device__ __forceinline__ void bar_group(int id) {
    asm volatile("bar.sync %0, 64;" :: "r"(id) : "memory");
}

// physical float4-window index within a dense 16-float row
__device__ __forceinline__ int swz(int row, int q) {
    return row * 16 + ((q ^ ((row >> 1) & 3)) << 2);
}

__global__ void __launch_bounds__(TPB, 16)
irnn_fused_kernel(const float* __restrict__ x,
                  const float* __restrict__ w_up,    const float* __restrict__ b_up,
                  const float* __restrict__ w_right, const float* __restrict__ b_right,
                  const float* __restrict__ w_down,  const float* __restrict__ b_down,
                  const float* __restrict__ w_left,  const float* __restrict__ b_left,
                  float* __restrict__ out)
{
    __shared__ float tiles[2][HR * CHUNK];   // dense, swizzled; 8 KB total

    const int bid = blockIdx.x;
    const int tid = threadIdx.x;

    if ((bid & 1) == 0) {
        // ---------------- vertical: one direction, one thread per column ----
        const int vb   = bid >> 1;          // 0 .. 1023
        const int isUp = vb & 1;            // 0 = down, 1 = up
        const int unit = vb >> 1;           // 0 .. 511

        const int id = unit * TPB + tid;    // 0 .. B*C*W-1 (65535)
        const int w  = id & (WW - 1);
        const int bc = id >> 8;
        const int c  = bc & (CC - 1);

        const float* xp = x + (size_t)bc * HW + w;

        if (!isUp) {
            float* od = out + 2 * DIRSZ + (size_t)bc * HW + w;   // down
            const float wd = w_down[c], bd = b_down[c];
            float s = xp[0];
            __stcs(&od[0], s);
#pragma unroll 8
            for (int h = 1; h < HH; ++h) {
                float xv = xp[h * WW];
                s = fmaxf(fmaf(wd, s, bd + xv), 0.0f);
                __stcs(&od[h * WW], s);
            }
        } else {
            float* ou = out + 0 * DIRSZ + (size_t)bc * HW + w;   // up
            const float wu = w_up[c], bu = b_up[c];
            float s = xp[(HH - 1) * WW];
            __stcs(&ou[(HH - 1) * WW], s);
#pragma unroll 8
            for (int h = HH - 2; h >= 0; --h) {
                float xv = xp[h * WW];
                s = fmaxf(fmaf(wu, s, bu + xv), 0.0f);
                __stcs(&ou[h * WW], s);
            }
        }
    } else {
        // --------------- horizontal: 64 rows, two 64-thread groups ----------
        const int hb = bid >> 1;                 // 0 .. 1023
        const int r0 = hb * HR;                  // first global row
        const int bc = hb >> 2;                  // = r0 >> 8, uniform in block
        const int c  = bc & (CC - 1);

        const bool isLeft = (tid >= HR);
        const int  gt     = tid & (HR - 1);      // owned row within tile
        const int  barid  = isLeft ? 2 : 1;

        const float* xbase = x + (size_t)r0 * WW;
        float* obase = out + (isLeft ? 3 : 1) * DIRSZ + (size_t)r0 * WW;

        const float wsc = isLeft ? w_left[c] : w_right[c];
        const float bsc = isLeft ? b_left[c] : b_right[c];

        float* tile = &tiles[isLeft ? 1 : 0][0];

        // staging map: f = k*64 + gt ; row = k*16 + (gt>>2) ; col4 = gt&3
        const int srow  = gt >> 2;               // 0..15, +16 per k
        const int scol4 = gt & 3;

        float s = 0.0f;
        for (int ch = 0; ch < NCHUNK; ++ch) {
            // right walks chunks forward, left backward
            const int wX = (isLeft ? (NCHUNK - 1 - ch) : ch) * CHUNK;

            // ---- load: LDG(64B) -> STS.128 swizzled (conflict-free) ----
#pragma unroll
            for (int k = 0; k < 4; ++k) {
                int row = srow + k * 16;
                float4 v = *(const float4*)&xbase[(size_t)row * WW + wX + scol4 * 4];
                *(float4*)&tile[swz(row, scol4)] = v;
            }
            bar_group(barid);

            // ---- scan owned row gt: 4 float4 windows ----
            if (!isLeft) {
#pragma unroll
                for (int q = 0; q < 4; ++q) {
                    float4 v = *(float4*)&tile[swz(gt, q)];
                    if (ch == 0 && q == 0) s = v.x;            // raw edge
                    else v.x = s = fmaxf(fmaf(wsc, s, bsc + v.x), 0.0f);
                    v.y = s = fmaxf(fmaf(wsc, s, bsc + v.y), 0.0f);
                    v.z = s = fmaxf(fmaf(wsc, s, bsc + v.z), 0.0f);
                    v.w = s = fmaxf(fmaf(wsc, s, bsc + v.w), 0.0f);
                    *(float4*)&tile[swz(gt, q)] = v;
                }
            } else {
#pragma unroll
                for (int q = 3; q >= 0; --q) {
                    float4 v = *(float4*)&tile[swz(gt, q)];
                    if (ch == 0 && q == 3) s = v.w;            // raw edge
                    else v.w = s = fmaxf(fmaf(wsc, s, bsc + v.w), 0.0f);
                    v.z = s = fmaxf(fmaf(wsc, s, bsc + v.z), 0.0f);
                    v.y = s = fmaxf(fmaf(wsc, s, bsc + v.y), 0.0f);
                    v.x = s = fmaxf(fmaf(wsc, s, bsc + v.x), 0.0f);
                    *(float4*)&tile[swz(gt, q)] = v;
                }
            }
            bar_group(barid);

            // ---- store: LDS.128 swizzled -> STG(64B) streaming ----
#pragma unroll
            for (int k = 0; k < 4; ++k) {
                int row = srow + k * 16;
                float4 v = *(float4*)&tile[swz(row, scol4)];
                __stcs((float4*)&obase[(size_t)row * WW + wX + scol4 * 4], v);
            }
            bar_group(barid);   // tile reads done before next chunk overwrites
        }
    }
}

extern "C" void kernel_launch(void* const* d_in, const int* in_sizes, int n_in,
                              void* d_out, int out_size)
{
    const float* x       = (const float*)d_in[0];
    const float* w_up    = (const float*)d_in[1];
    const float* w_right = (const float*)d_in[2];
    const float* w_down  = (const float*)d_in[3];
    const float* w_left  = (const float*)d_in[4];
    const float* b_up    = (const float*)d_in[5];
    const float* b_right = (const float*)d_in[6];
    const float* b_down  = (const float*)d_in[7];
    const float* b_left  = (const float*)d_in[8];
    float* out = (float*)d_out;

    // 1024 vertical (512 down + 512 up) + 1024 horizontal (64 rows, R+L),
    // parity-interleaved: 2048 blocks x 128 threads, single wave @16/SM.
    irnn_fused_kernel<<<2048, TPB>>>(x,
                                     w_up, b_up, w_right, b_right,
                                     w_down, b_down, w_left, b_left,
                                     out);
}

// round 15
// speedup vs baseline: 1.8129x; 1.2412x over previous
#include <cuda_runtime.h>

// Spacial IRNN: 4 directional relu-scans over [B,C,H,W] = [4,64,256,256] fp32.
// out[dir][b][c][h][w], dir: 0=up, 1=right, 2=down, 3=left.
// h_0 = x_edge (raw), h_t = relu(w_c * h_{t-1} + b_c + x_t).
//
// R9 chassis (best: 75.8us) with the h-path store phase FUSED with the next
// chunk's load phase (same thread owns each tile slot in both phases ->
// same-thread ordering, no barrier needed between them). 2 barriers/chunk.
//   role = bid & 1:
//     0 -> vertical block, one direction per block (vb&1: 0=down, 1=up),
//          one thread per column, scalar coalesced I/O, stcs stores.
//     1 -> horizontal block: warp-specialized, threads 0-127 "right" on
//          tile A (bar 1), 128-255 "left" on tile B (bar 2); float4 I/O on
//          stride-36 tiles, 8-float register scan windows, stcs stores.

#define HH 256
#define WW 256
#define BB 4
#define CC 64

constexpr int HW = HH * WW;
constexpr long long DIRSZ = (long long)BB * CC * HH * WW;  // 16,777,216

constexpr int TPB    = 256;
constexpr int HROWS  = 128;
constexpr int CHUNK  = 32;
constexpr int NCHUNK = WW / CHUNK;              // 8
constexpr int STRIDE = 36;                      // floats; 144B row, 16B-aligned

__device__ __forceinline__ void bar_group(int id) {
    asm volatile("bar.sync %0, 128;" :: "r"(id) : "memory");
}

__global__ void __launch_bounds__(TPB, 6)
irnn_fused_kernel(const float* __restrict__ x,
                  const float* __restrict__ w_up,    const float* __restrict__ b_up,
                  const float* __restrict__ w_right, const float* __restrict__ b_right,
                  const float* __restrict__ w_down,  const float* __restrict__ b_down,
                  const float* __restrict__ w_left,  const float* __restrict__ b_left,
                  float* __restrict__ out)
{
    __shared__ float tiles[2][HROWS * STRIDE];   // [0]=right(A), [1]=left(B)

    const int bid = blockIdx.x;
    const int tid = threadIdx.x;

    if ((bid & 1) == 0) {
        // ---------------- vertical: one direction, one thread per column ----
        const int vb   = bid >> 1;          // 0 .. 511
        const int isUp = vb & 1;            // 0 = down, 1 = up
        const int unit = vb >> 1;           // 0 .. 255

        const int id = unit * TPB + tid;    // 0 .. B*C*W-1
        const int w  = id & (WW - 1);
        const int bc = id >> 8;
        const int c  = bc & (CC - 1);

        const float* xp = x + (size_t)bc * HW + w;

        if (!isUp) {
            float* od = out + 2 * DIRSZ + (size_t)bc * HW + w;   // down
            const float wd = w_down[c], bd = b_down[c];
            float s = xp[0];
            __stcs(&od[0], s);
#pragma unroll 8
            for (int h = 1; h < HH; ++h) {
                float xv = xp[h * WW];
                s = fmaxf(fmaf(wd, s, bd + xv), 0.0f);
                __stcs(&od[h * WW], s);
            }
        } else {
            float* ou = out + 0 * DIRSZ + (size_t)bc * HW + w;   // up
            const float wu = w_up[c], bu = b_up[c];
            float s = xp[(HH - 1) * WW];
            __stcs(&ou[(HH - 1) * WW], s);
#pragma unroll 8
            for (int h = HH - 2; h >= 0; --h) {
                float xv = xp[h * WW];
                s = fmaxf(fmaf(wu, s, bu + xv), 0.0f);
                __stcs(&ou[h * WW], s);
            }
        }
    } else {
        // ------------------- horizontal: 128 rows, warp-specialized ---------
        const int hb = bid >> 1;                 // 0 .. 511
        const int r0 = hb * HROWS;               // first global row
        const int bc = r0 >> 8;                  // uniform within block
        const int c  = bc & (CC - 1);

        const bool isLeft = (tid >= HROWS);
        const int  gt     = tid & (HROWS - 1);   // thread id within group
        const int  barid  = isLeft ? 2 : 1;

        const float* xbase = x + (size_t)r0 * WW;
        float* obase = out + (isLeft ? 3 : 1) * DIRSZ + (size_t)r0 * WW;

        const float wsc = isLeft ? w_left[c] : w_right[c];
        const float bsc = isLeft ? b_left[c] : b_right[c];

        float* tile = &tiles[isLeft ? 1 : 0][0];

        // staging map: f = k*128 + gt ; row = f>>3 ; col4 = f&7
        // The SAME thread owns slot (row,col4) in load and store phases.
        const int srow  = gt >> 3;               // base row, +16 per k
        const int scol4 = gt & 7;

        // ---- prologue: load chunk 0 ----
        {
            const int wX = (isLeft ? (NCHUNK - 1) : 0) * CHUNK;
#pragma unroll
            for (int k = 0; k < 8; ++k) {
                int row = srow + k * 16;
                float4 v = *(const float4*)&xbase[(size_t)row * WW + wX + scol4 * 4];
                *(float4*)&tile[row * STRIDE + scol4 * 4] = v;
            }
        }
        bar_group(barid);

        float s = 0.0f;
        for (int ch = 0; ch < NCHUNK; ++ch) {
            const int wX = (isLeft ? (NCHUNK - 1 - ch) : ch) * CHUNK;

            // ---- scan owned row gt, register-resident in 8-float windows ---
            float* tr = &tile[gt * STRIDE];
            if (!isLeft) {
#pragma unroll
                for (int sb = 0; sb < 4; ++sb) {        // 4 sub-blocks of 8
                    float4 v0 = *(float4*)&tr[sb * 8];
                    float4 v1 = *(float4*)&tr[sb * 8 + 4];
                    float a[8] = {v0.x, v0.y, v0.z, v0.w, v1.x, v1.y, v1.z, v1.w};
#pragma unroll
                    for (int t = 0; t < 8; ++t) {
                        float xv = a[t];
                        if (ch == 0 && sb == 0 && t == 0) s = xv;   // raw edge
                        else s = fmaxf(fmaf(wsc, s, bsc + xv), 0.0f);
                        a[t] = s;
                    }
                    *(float4*)&tr[sb * 8]     = make_float4(a[0], a[1], a[2], a[3]);
                    *(float4*)&tr[sb * 8 + 4] = make_float4(a[4], a[5], a[6], a[7]);
                }
            } else {
#pragma unroll
                for (int sb = 3; sb >= 0; --sb) {
                    float4 v0 = *(float4*)&tr[sb * 8];
                    float4 v1 = *(float4*)&tr[sb * 8 + 4];
                    float a[8] = {v0.x, v0.y, v0.z, v0.w, v1.x, v1.y, v1.z, v1.w};
#pragma unroll
                    for (int t = 7; t >= 0; --t) {
                        float xv = a[t];
                        if (ch == 0 && sb == 3 && t == 7) s = xv;   // raw edge
                        else s = fmaxf(fmaf(wsc, s, bsc + xv), 0.0f);
                        a[t] = s;
                    }
                    *(float4*)&tr[sb * 8]     = make_float4(a[0], a[1], a[2], a[3]);
                    *(float4*)&tr[sb * 8 + 4] = make_float4(a[4], a[5], a[6], a[7]);
                }
            }
            bar_group(barid);   // scan results visible to staging threads

            // ---- fused store(ch) + load(ch+1): slot owner does both --------
            if (ch < NCHUNK - 1) {
                const int chn = ch + 1;
                const int wN  = (isLeft ? (NCHUNK - 1 - chn) : chn) * CHUNK;
                // two half-batches of 4 to bound live registers
#pragma unroll
                for (int hhf = 0; hhf < 2; ++hhf) {
                    float4 oldv[4], newv[4];
#pragma unroll
                    for (int k = 0; k < 4; ++k) {
                        int row = srow + (hhf * 4 + k) * 16;
                        oldv[k] = *(float4*)&tile[row * STRIDE + scol4 * 4];
                        newv[k] = *(const float4*)&xbase[(size_t)row * WW + wN + scol4 * 4];
                    }
#pragma unroll
                    for (int k = 0; k < 4; ++k) {
                        int row = srow + (hhf * 4 + k) * 16;
                        __stcs((float4*)&obase[(size_t)row * WW + wX + scol4 * 4], oldv[k]);
                        *(float4*)&tile[row * STRIDE + scol4 * 4] = newv[k];
                    }
                }
                bar_group(barid);   // new chunk staged before next scan
            } else {
                // last chunk: store only
#pragma unroll
                for (int k = 0; k < 8; ++k) {
                    int row = srow + k * 16;
                    float4 v = *(float4*)&tile[row * STRIDE + scol4 * 4];
                    __stcs((float4*)&obase[(size_t)row * WW + wX + scol4 * 4], v);
                }
            }
        }
    }
}

extern "C" void kernel_launch(void* const* d_in, const int* in_sizes, int n_in,
                              void* d_out, int out_size)
{
    const float* x       = (const float*)d_in[0];
    const float* w_up    = (const float*)d_in[1];
    const float* w_right = (const float*)d_in[2];
    const float* w_down  = (const float*)d_in[3];
    const float* w_left  = (const float*)d_in[4];
    const float* b_up    = (const float*)d_in[5];
    const float* b_right = (const float*)d_in[6];
    const float* b_down  = (const float*)d_in[7];
    const float* b_left  = (const float*)d_in[8];
    float* out = (float*)d_out;

    // 512 vertical (256 down + 256 up) + 512 horizontal, interleaved by parity
    irnn_fused_kernel<<<1024, TPB>>>(x,
                                     w_up, b_up, w_right, b_right,
                                     w_down, b_down, w_left, b_left,
                                     out);
}